// round 7
// baseline (speedup 1.0000x reference)
#include <cuda_runtime.h>
#include <cuda_bf16.h>
#include <cstdint>

typedef unsigned long long ull;
typedef uint32_t u32;

#define ROWS_IMG 12996          // 114*114 padded pixels per image
#define GUARD    128
#define TAIL     256
#define TOT_ROWS (GUARD + 32 * ROWS_IMG + TAIL)

// scratch: [row][192 s8] : digit0(64 ci) | digit1(64) | digit2(64)
__device__ __align__(16) signed char g_scratch[(size_t)TOT_ROWS * 192];
__device__ __align__(16) signed char g_wsign[9 * 64 * 64];   // [tap][co][ci] in {-1,0,1}
__device__ float g_wscale[64];                               // pow2 per-co scale

// ---------------- helpers ----------------
__device__ __forceinline__ u32 smem_u32(const void* p) {
    u32 a;
    asm("{ .reg .u64 t; cvta.to.shared.u64 t, %1; cvt.u32.u64 %0, t; }" : "=r"(a) : "l"(p));
    return a;
}
__device__ __forceinline__ void cp16(u32 dst, const void* src) {
    asm volatile("cp.async.cg.shared.global [%0], [%1], 16;" :: "r"(dst), "l"(src));
}
#define CP_COMMIT() asm volatile("cp.async.commit_group;" ::: "memory")

__device__ __forceinline__ void ldm4(u32* r, u32 addr) {
    asm volatile("ldmatrix.sync.aligned.m8n8.x4.shared.b16 {%0,%1,%2,%3}, [%4];"
                 : "=r"(r[0]), "=r"(r[1]), "=r"(r[2]), "=r"(r[3]) : "r"(addr));
}
__device__ __forceinline__ void imma16832(int* c, const u32* a, u32 b0, u32 b1) {
    asm volatile(
        "mma.sync.aligned.m16n8k32.row.col.s32.s8.s8.s32 "
        "{%0,%1,%2,%3}, {%4,%5,%6,%7}, {%8,%9}, {%0,%1,%2,%3};"
        : "+r"(c[0]), "+r"(c[1]), "+r"(c[2]), "+r"(c[3])
        : "r"(a[0]), "r"(a[1]), "r"(a[2]), "r"(a[3]), "r"(b0), "r"(b1));
}

// ---------------------------------------------------------------------------
// Kernel 1: binarize weights -> s8 sign [tap][co][ci] + pow2 scale per co
// ---------------------------------------------------------------------------
__global__ void binarize_kernel(const float* __restrict__ w) {
    __shared__ float rb[18], rb2[18], rb3[18];
    __shared__ float s_mean, s_scale;
    const int co = blockIdx.x;
    const int e = threadIdx.x;           // e = ci*9 + tap
    const int lane = e & 31, wid = e >> 5;
    const float v = w[co * 576 + e];

    float s = v;
    #pragma unroll
    for (int o = 16; o > 0; o >>= 1) s += __shfl_down_sync(0xffffffffu, s, o);
    if (lane == 0) rb[wid] = s;
    __syncthreads();
    if (e == 0) {
        float t = 0.f;
        for (int i = 0; i < 18; ++i) t += rb[i];
        s_mean = t * (1.0f / 576.0f);
    }
    __syncthreads();
    const float d = v - s_mean;
    float sq = d * d, ab = fabsf(d);
    #pragma unroll
    for (int o = 16; o > 0; o >>= 1) {
        sq += __shfl_down_sync(0xffffffffu, sq, o);
        ab += __shfl_down_sync(0xffffffffu, ab, o);
    }
    if (lane == 0) { rb2[wid] = sq; rb3[wid] = ab; }
    __syncthreads();
    if (e == 0) {
        float t2 = 0.f, t3 = 0.f;
        for (int i = 0; i < 18; ++i) { t2 += rb2[i]; t3 += rb3[i]; }
        const float stdv = sqrtf(t2 / 575.0f);
        const float mean_abs = t3 / (576.0f * stdv);
        s_scale = exp2f(rintf(log2f(mean_abs)));
    }
    __syncthreads();
    const signed char sg = (d > 0.f) ? 1 : ((d < 0.f) ? -1 : 0);
    const int tap = e % 9, ci = e / 9;
    g_wsign[(tap * 64 + co) * 64 + ci] = sg;
    if (e == 0) g_wscale[co] = s_scale;
}

// ---------------------------------------------------------------------------
// Kernel 2: zero padding regions of scratch (incl. head guard + tail)
// 192 B/row = 12 uint4
// ---------------------------------------------------------------------------
__global__ void pad_zero_kernel() {
    uint4* base = reinterpret_cast<uint4*>(g_scratch);
    const uint4 z = make_uint4(0, 0, 0, 0);
    if (blockIdx.x == 32) {
        for (int i = threadIdx.x; i < GUARD * 12; i += blockDim.x) base[i] = z;
        uint4* tail = base + ((size_t)GUARD + 32 * (size_t)ROWS_IMG) * 12;
        for (int i = threadIdx.x; i < TAIL * 12; i += blockDim.x) tail[i] = z;
        return;
    }
    const int n = blockIdx.x;
    const size_t imgrow0 = GUARD + (size_t)n * ROWS_IMG;
    for (int i = threadIdx.x; i < 228 * 12; i += blockDim.x) {
        const int r = i / 12, c = i % 12;
        const size_t row = imgrow0 + (r < 114 ? r : (12882 - 114 + r));
        base[row * 12 + c] = z;
    }
    for (int i = threadIdx.x; i < 112 * 2 * 12; i += blockDim.x) {
        const int rp  = 1 + i / 24;
        const int col = 112 + ((i / 12) & 1);
        const int c   = i % 12;
        base[(imgrow0 + (size_t)rp * 114 + col) * 12 + c] = z;
    }
}

// ---------------------------------------------------------------------------
// Kernel 3: convert x fp32 -> exact 3x s8 digit scratch rows
// x = d0*2^-4 + d1*2^-11 + d2*2^-18 + eps, |eps| <= 2^-19
// ---------------------------------------------------------------------------
__global__ void convert_kernel(const float* __restrict__ x) {
    __shared__ float sm[64][33];
    const int n = blockIdx.y;
    const int q0 = blockIdx.x * 32;
    const int t = threadIdx.x;
    const int w8 = t >> 5, l = t & 31;
    #pragma unroll
    for (int r = 0; r < 8; ++r) {
        const int ci = w8 * 8 + r;
        sm[ci][l] = x[((size_t)n * 64 + ci) * 12544 + q0 + l];
    }
    __syncthreads();
    const int pix = t >> 3, g = t & 7;
    const int q = q0 + pix;
    const int r = q / 112, c = q - r * 112;
    const size_t row = GUARD + (size_t)n * ROWS_IMG + (size_t)(r + 1) * 114 + c;
    signed char* dst = g_scratch + row * 192 + g * 8;

    union { signed char b[8]; ull u; } p0, p1, p2;
    #pragma unroll
    for (int i = 0; i < 8; ++i) {
        const float f = sm[g * 8 + i][pix];
        float a0 = fminf(127.f, fmaxf(-128.f, rintf(f * 16.f)));
        const float r1 = fmaf(a0, -0.0625f, f);
        float a1 = fminf(127.f, fmaxf(-127.f, rintf(r1 * 2048.f)));
        const float r2 = fmaf(a1, -4.8828125e-4f, r1);
        float a2 = fminf(127.f, fmaxf(-127.f, rintf(r2 * 262144.f)));
        p0.b[i] = (signed char)(int)a0;
        p1.b[i] = (signed char)(int)a1;
        p2.b[i] = (signed char)(int)a2;
    }
    *reinterpret_cast<ull*>(dst)       = p0.u;
    *reinterpret_cast<ull*>(dst + 64)  = p1.u;
    *reinterpret_cast<ull*>(dst + 128) = p2.u;
}

// ---------------------------------------------------------------------------
// Kernel 4: implicit-GEMM conv via mma.sync m16n8k32 s8 + LUT bucketize
// Block: 256 threads (8 warps), tile M=256 px x N=64 co, digit-outer loop.
// ---------------------------------------------------------------------------
#define AROWS  486
#define APITCH 208
#define A_OFF  0
#define B_OFF  101120                    // 486*208 = 101088, pad
#define BPITCH 80
#define BTAP   (64 * 80)                 // 5120
#define LUT_OFF (B_OFF + 9 * BTAP)       // 147200
#define WS_OFF  (LUT_OFF + 1792)         // 148992
#define SMEM_TOTAL (WS_OFF + 256 + 64)   // 149312

__global__ void __launch_bounds__(256, 1)
conv_mma_kernel(const float* __restrict__ lut, float* __restrict__ out) {
    extern __shared__ __align__(1024) char smem[];
    const u32 sb = smem_u32(smem);
    const int tid = threadIdx.x, warp = tid >> 5, lane = tid & 31;
    const int tile = blockIdx.x, n = blockIdx.y;
    const int s0 = 114 + tile * 256;
    const size_t imgrow0 = GUARD + (size_t)n * ROWS_IMG;
    const long g0 = (long)s0 - 115;

    // ---- stage B: 9 taps x 64 co rows x 64B, pitch 80 (ldmatrix-conflict-free)
    {
        const char* wsrc = reinterpret_cast<const char*>(g_wsign);
        for (int i = tid; i < 9 * 64 * 4; i += 256) {
            const int tap = i >> 8, r = (i >> 2) & 63, c = i & 3;
            cp16(sb + B_OFF + tap * BTAP + r * BPITCH + c * 16,
                 wsrc + (size_t)(tap * 64 + r) * 64 + c * 16);
        }
    }
    for (int i = tid; i < 448; i += 256)
        reinterpret_cast<float*>(smem + LUT_OFF)[i] = lut[i];
    if (tid < 64)
        reinterpret_cast<float*>(smem + WS_OFF)[tid] = g_wscale[tid];

    // ---- stage A: 486 rows x 192B (pitch 208)
    const char* abase = reinterpret_cast<const char*>(g_scratch) +
                        ((size_t)imgrow0 + g0) * 192;
    for (int i = tid; i < 486 * 12; i += 256) {
        const int r = i / 12, c = i - r * 12;
        cp16(sb + A_OFF + r * APITCH + c * 16, abase + (size_t)r * 192 + c * 16);
    }
    CP_COMMIT();
    asm volatile("cp.async.wait_group 0;" ::: "memory");
    __syncthreads();

    // ---- mainloop: digit-outer, s32 IMMA chains, f32 merge ----
    const int laneR = lane & 15;
    const int blk   = lane >> 4;
    const u32 abase_t = sb + A_OFF + (warp * 32 + laneR) * APITCH + blk * 16;
    const u32 bbase_t = sb + B_OFF + laneR * BPITCH + blk * 16;

    float facc[2][8][4];
    #pragma unroll
    for (int mt = 0; mt < 2; ++mt)
        #pragma unroll
        for (int nt = 0; nt < 8; ++nt)
            #pragma unroll
            for (int i = 0; i < 4; ++i) facc[mt][nt][i] = 0.f;

    #pragma unroll
    for (int d = 0; d < 3; ++d) {
        int sacc[2][8][4];
        #pragma unroll
        for (int mt = 0; mt < 2; ++mt)
            #pragma unroll
            for (int nt = 0; nt < 8; ++nt)
                #pragma unroll
                for (int i = 0; i < 4; ++i) sacc[mt][nt][i] = 0;

        #pragma unroll
        for (int kh = 0; kh < 3; ++kh) {
            #pragma unroll
            for (int kw = 0; kw < 3; ++kw) {
                const int tap = kh * 3 + kw;
                #pragma unroll
                for (int kc = 0; kc < 2; ++kc) {
                    u32 br[16];
                    const u32 bk = bbase_t + tap * BTAP + kc * 32;
                    ldm4(&br[0],  bk);
                    ldm4(&br[4],  bk + 16 * BPITCH);
                    ldm4(&br[8],  bk + 32 * BPITCH);
                    ldm4(&br[12], bk + 48 * BPITCH);
                    u32 a0[4], a1[4];
                    const u32 ka = abase_t + (kh * 114 + kw) * APITCH + d * 64 + kc * 32;
                    ldm4(a0, ka);
                    ldm4(a1, ka + 16 * APITCH);
                    #pragma unroll
                    for (int nt2 = 0; nt2 < 4; ++nt2) {
                        imma16832(sacc[0][2 * nt2],     a0, br[nt2 * 4],     br[nt2 * 4 + 2]);
                        imma16832(sacc[0][2 * nt2 + 1], a0, br[nt2 * 4 + 1], br[nt2 * 4 + 3]);
                    }
                    #pragma unroll
                    for (int nt2 = 0; nt2 < 4; ++nt2) {
                        imma16832(sacc[1][2 * nt2],     a1, br[nt2 * 4],     br[nt2 * 4 + 2]);
                        imma16832(sacc[1][2 * nt2 + 1], a1, br[nt2 * 4 + 1], br[nt2 * 4 + 3]);
                    }
                }
            }
        }
        const float sc = (d == 0) ? 0.0625f
                       : (d == 1) ? 4.8828125e-4f : 3.814697265625e-6f;
        #pragma unroll
        for (int mt = 0; mt < 2; ++mt)
            #pragma unroll
            for (int nt = 0; nt < 8; ++nt)
                #pragma unroll
                for (int i = 0; i < 4; ++i)
                    facc[mt][nt][i] = fmaf(sc, (float)sacc[mt][nt][i], facc[mt][nt][i]);
    }

    // ---- epilogue: facc -> smem [px][65], scale + LUT bucketize, store ----
    __syncthreads();
    float* sum = reinterpret_cast<float*>(smem);
    #pragma unroll
    for (int mt = 0; mt < 2; ++mt)
        #pragma unroll
        for (int nt = 0; nt < 8; ++nt)
            #pragma unroll
            for (int i = 0; i < 4; ++i) {
                const int row = warp * 32 + mt * 16 + (lane >> 2) + ((i >> 1) << 3);
                const int col = nt * 8 + ((lane & 3) << 1) + (i & 1);
                sum[row * 65 + col] = facc[mt][nt][i];
            }
    __syncthreads();

    const int j = tid;
    const int s = s0 + j;
    const int rimg = s / 114 - 1;
    const int c = s - (rimg + 1) * 114;
    if (c < 112 && rimg < 112) {
        const int q = rimg * 112 + c;
        float* op = out + (size_t)n * 64 * 12544 + q;
        const float* sl = reinterpret_cast<const float*>(smem + LUT_OFF);
        const float* ws = reinterpret_cast<const float*>(smem + WS_OFF);
        #pragma unroll 4
        for (int co = 0; co < 64; ++co) {
            const float v = sum[j * 65 + co] * ws[co];
            const float* tt = sl + co * 7;
            const float t0 = tt[0], t1 = tt[1], t2 = tt[2], t3 = tt[3],
                        t4 = tt[4], t5 = tt[5], t6 = tt[6];
            float r = v;
            if (v <= t0)            r = 0.f;
            if (v > t0 && v < t1)   r = 1.f;
            if (v >= t1 && v <= t2) r = 2.f;
            if (v > t2 && v < t3)   r = 3.f;
            if (v >= t3 && v <= t4) r = 4.f;
            if (v > t4 && v < t5)   r = 5.f;
            if (v >= t5 && v <= t6) r = 6.f;
            if (v > t6)             r = 7.f;
            op[(size_t)co * 12544] = r;
        }
    }
}

// ---------------------------------------------------------------------------
extern "C" void kernel_launch(void* const* d_in, const int* in_sizes, int n_in,
                              void* d_out, int out_size) {
    (void)in_sizes; (void)n_in; (void)out_size;
    const float* x   = (const float*)d_in[0];
    const float* w   = (const float*)d_in[1];
    const float* lut = (const float*)d_in[2];
    float* out = (float*)d_out;

    cudaFuncSetAttribute(conv_mma_kernel,
                         cudaFuncAttributeMaxDynamicSharedMemorySize, SMEM_TOTAL);

    binarize_kernel<<<64, 576>>>(w);
    pad_zero_kernel<<<33, 256>>>();
    convert_kernel<<<dim3(392, 32), 256>>>(x);
    conv_mma_kernel<<<dim3(50, 32), 256, SMEM_TOTAL>>>(lut, out);
}

// round 8
// speedup vs baseline: 1.2815x; 1.2815x over previous
#include <cuda_runtime.h>
#include <cuda_bf16.h>
#include <cstdint>

typedef unsigned long long ull;
typedef uint32_t u32;

#define ROWS_IMG 12996          // 114*114 padded pixels per image
#define GUARD    128
#define TAIL     256
#define TOT_ROWS (GUARD + 32 * ROWS_IMG + TAIL)

// scratch: [row][192 s8] : digit0(64 ci) | digit1(64) | digit2(64)
__device__ __align__(16) signed char g_scratch[(size_t)TOT_ROWS * 192];
__device__ __align__(16) signed char g_wsign[9 * 64 * 64];   // [tap][co][ci] in {-1,0,1}
__device__ float g_wscale[64];                               // pow2 per-co scale

// ---------------- helpers ----------------
__device__ __forceinline__ u32 smem_u32(const void* p) {
    u32 a;
    asm("{ .reg .u64 t; cvta.to.shared.u64 t, %1; cvt.u32.u64 %0, t; }" : "=r"(a) : "l"(p));
    return a;
}
__device__ __forceinline__ void cp16(u32 dst, const void* src) {
    asm volatile("cp.async.cg.shared.global [%0], [%1], 16;" :: "r"(dst), "l"(src));
}
#define CP_COMMIT() asm volatile("cp.async.commit_group;" ::: "memory")

__device__ __forceinline__ void ldm4(u32* r, u32 addr) {
    asm volatile("ldmatrix.sync.aligned.m8n8.x4.shared.b16 {%0,%1,%2,%3}, [%4];"
                 : "=r"(r[0]), "=r"(r[1]), "=r"(r[2]), "=r"(r[3]) : "r"(addr));
}
__device__ __forceinline__ void imma16832(int* c, const u32* a, u32 b0, u32 b1) {
    asm volatile(
        "mma.sync.aligned.m16n8k32.row.col.s32.s8.s8.s32 "
        "{%0,%1,%2,%3}, {%4,%5,%6,%7}, {%8,%9}, {%0,%1,%2,%3};"
        : "+r"(c[0]), "+r"(c[1]), "+r"(c[2]), "+r"(c[3])
        : "r"(a[0]), "r"(a[1]), "r"(a[2]), "r"(a[3]), "r"(b0), "r"(b1));
}

// ---------------------------------------------------------------------------
// Kernel 1: binarize weights -> s8 sign [tap][co][ci] + pow2 scale per co
// ---------------------------------------------------------------------------
__global__ void binarize_kernel(const float* __restrict__ w) {
    __shared__ float rb[18], rb2[18], rb3[18];
    __shared__ float s_mean, s_scale;
    const int co = blockIdx.x;
    const int e = threadIdx.x;           // e = ci*9 + tap
    const int lane = e & 31, wid = e >> 5;
    const float v = w[co * 576 + e];

    float s = v;
    #pragma unroll
    for (int o = 16; o > 0; o >>= 1) s += __shfl_down_sync(0xffffffffu, s, o);
    if (lane == 0) rb[wid] = s;
    __syncthreads();
    if (e == 0) {
        float t = 0.f;
        for (int i = 0; i < 18; ++i) t += rb[i];
        s_mean = t * (1.0f / 576.0f);
    }
    __syncthreads();
    const float d = v - s_mean;
    float sq = d * d, ab = fabsf(d);
    #pragma unroll
    for (int o = 16; o > 0; o >>= 1) {
        sq += __shfl_down_sync(0xffffffffu, sq, o);
        ab += __shfl_down_sync(0xffffffffu, ab, o);
    }
    if (lane == 0) { rb2[wid] = sq; rb3[wid] = ab; }
    __syncthreads();
    if (e == 0) {
        float t2 = 0.f, t3 = 0.f;
        for (int i = 0; i < 18; ++i) { t2 += rb2[i]; t3 += rb3[i]; }
        const float stdv = sqrtf(t2 / 575.0f);
        const float mean_abs = t3 / (576.0f * stdv);
        s_scale = exp2f(rintf(log2f(mean_abs)));
    }
    __syncthreads();
    const signed char sg = (d > 0.f) ? 1 : ((d < 0.f) ? -1 : 0);
    const int tap = e % 9, ci = e / 9;
    g_wsign[(tap * 64 + co) * 64 + ci] = sg;
    if (e == 0) g_wscale[co] = s_scale;
}

// ---------------------------------------------------------------------------
// Kernel 2: zero padding regions of scratch (192 B/row = 12 uint4)
// ---------------------------------------------------------------------------
__global__ void pad_zero_kernel() {
    uint4* base = reinterpret_cast<uint4*>(g_scratch);
    const uint4 z = make_uint4(0, 0, 0, 0);
    if (blockIdx.x == 32) {
        for (int i = threadIdx.x; i < GUARD * 12; i += blockDim.x) base[i] = z;
        uint4* tail = base + ((size_t)GUARD + 32 * (size_t)ROWS_IMG) * 12;
        for (int i = threadIdx.x; i < TAIL * 12; i += blockDim.x) tail[i] = z;
        return;
    }
    const int n = blockIdx.x;
    const size_t imgrow0 = GUARD + (size_t)n * ROWS_IMG;
    for (int i = threadIdx.x; i < 228 * 12; i += blockDim.x) {
        const int r = i / 12, c = i % 12;
        const size_t row = imgrow0 + (r < 114 ? r : (12882 - 114 + r));
        base[row * 12 + c] = z;
    }
    for (int i = threadIdx.x; i < 112 * 2 * 12; i += blockDim.x) {
        const int rp  = 1 + i / 24;
        const int col = 112 + ((i / 12) & 1);
        const int c   = i % 12;
        base[(imgrow0 + (size_t)rp * 114 + col) * 12 + c] = z;
    }
}

// ---------------------------------------------------------------------------
// Kernel 3: convert x fp32 -> exact 3x s8 digit scratch rows
// x = d0*2^-4 + d1*2^-11 + d2*2^-18 + eps, |eps| <= 2^-19
// ---------------------------------------------------------------------------
__global__ void convert_kernel(const float* __restrict__ x) {
    __shared__ float sm[64][33];
    const int n = blockIdx.y;
    const int q0 = blockIdx.x * 32;
    const int t = threadIdx.x;
    const int w8 = t >> 5, l = t & 31;
    #pragma unroll
    for (int r = 0; r < 8; ++r) {
        const int ci = w8 * 8 + r;
        sm[ci][l] = x[((size_t)n * 64 + ci) * 12544 + q0 + l];
    }
    __syncthreads();
    const int pix = t >> 3, g = t & 7;
    const int q = q0 + pix;
    const int r = q / 112, c = q - r * 112;
    const size_t row = GUARD + (size_t)n * ROWS_IMG + (size_t)(r + 1) * 114 + c;
    signed char* dst = g_scratch + row * 192 + g * 8;

    union { signed char b[8]; ull u; } p0, p1, p2;
    #pragma unroll
    for (int i = 0; i < 8; ++i) {
        const float f = sm[g * 8 + i][pix];
        float a0 = fminf(127.f, fmaxf(-128.f, rintf(f * 16.f)));
        const float r1 = fmaf(a0, -0.0625f, f);
        float a1 = fminf(127.f, fmaxf(-127.f, rintf(r1 * 2048.f)));
        const float r2 = fmaf(a1, -4.8828125e-4f, r1);
        float a2 = fminf(127.f, fmaxf(-127.f, rintf(r2 * 262144.f)));
        p0.b[i] = (signed char)(int)a0;
        p1.b[i] = (signed char)(int)a1;
        p2.b[i] = (signed char)(int)a2;
    }
    *reinterpret_cast<ull*>(dst)       = p0.u;
    *reinterpret_cast<ull*>(dst + 64)  = p1.u;
    *reinterpret_cast<ull*>(dst + 128) = p2.u;
}

// ---------------------------------------------------------------------------
// Kernel 4: implicit-GEMM conv via mma.sync m16n8k32 s8 + LUT bucketize
// Block: 512 threads (16 warps, 4/SMSP), tile M=256 px x N=64 co.
// Warp owns 16 rows. Digit-outer loop; A staged per-digit in 3 cp groups.
// ---------------------------------------------------------------------------
#define AROWS  486
#define APITCH 208
#define A_OFF  0
#define B_OFF  101120                    // 486*208 = 101088, pad
#define BPITCH 80
#define BTAP   (64 * 80)                 // 5120
#define LUT_OFF (B_OFF + 9 * BTAP)       // 147200
#define WS_OFF  (LUT_OFF + 1792)         // 148992
#define SMEM_TOTAL (WS_OFF + 256 + 64)   // 149312

__global__ void __launch_bounds__(512, 1)
conv_mma_kernel(const float* __restrict__ lut, float* __restrict__ out) {
    extern __shared__ __align__(1024) char smem[];
    const u32 sb = smem_u32(smem);
    const int tid = threadIdx.x, warp = tid >> 5, lane = tid & 31;
    const int tile = blockIdx.x, n = blockIdx.y;
    const int s0 = 114 + tile * 256;
    const size_t imgrow0 = GUARD + (size_t)n * ROWS_IMG;
    const long g0 = (long)s0 - 115;

    const char* abase = reinterpret_cast<const char*>(g_scratch) +
                        ((size_t)imgrow0 + g0) * 192;

    // ---- group 1: B tiles + LUT + scales + A digit-0 ----
    {
        const char* wsrc = reinterpret_cast<const char*>(g_wsign);
        for (int i = tid; i < 9 * 64 * 4; i += 512) {
            const int tap = i >> 8, r = (i >> 2) & 63, c = i & 3;
            cp16(sb + B_OFF + tap * BTAP + r * BPITCH + c * 16,
                 wsrc + (size_t)(tap * 64 + r) * 64 + c * 16);
        }
        for (int i = tid; i < 486 * 4; i += 512) {
            const int r = i >> 2, c = i & 3;
            cp16(sb + A_OFF + r * APITCH + c * 16, abase + (size_t)r * 192 + c * 16);
        }
    }
    for (int i = tid; i < 448; i += 512)
        reinterpret_cast<float*>(smem + LUT_OFF)[i] = lut[i];
    if (tid < 64)
        reinterpret_cast<float*>(smem + WS_OFF)[tid] = g_wscale[tid];
    CP_COMMIT();
    // ---- group 2: A digit-1 ----
    for (int i = tid; i < 486 * 4; i += 512) {
        const int r = i >> 2, c = (i & 3) + 4;
        cp16(sb + A_OFF + r * APITCH + c * 16, abase + (size_t)r * 192 + c * 16);
    }
    CP_COMMIT();
    // ---- group 3: A digit-2 ----
    for (int i = tid; i < 486 * 4; i += 512) {
        const int r = i >> 2, c = (i & 3) + 8;
        cp16(sb + A_OFF + r * APITCH + c * 16, abase + (size_t)r * 192 + c * 16);
    }
    CP_COMMIT();

    // ---- mainloop: digit-outer, s32 IMMA chains, f32 merge ----
    const int laneR = lane & 15;
    const int blk   = lane >> 4;
    const u32 abase_t = sb + A_OFF + (warp * 16 + laneR) * APITCH + blk * 16;
    const u32 bbase_t = sb + B_OFF + laneR * BPITCH + blk * 16;

    float facc[8][4];
    #pragma unroll
    for (int nt = 0; nt < 8; ++nt)
        #pragma unroll
        for (int i = 0; i < 4; ++i) facc[nt][i] = 0.f;

    #pragma unroll
    for (int d = 0; d < 3; ++d) {
        if (d == 0)      asm volatile("cp.async.wait_group 2;" ::: "memory");
        else if (d == 1) asm volatile("cp.async.wait_group 1;" ::: "memory");
        else             asm volatile("cp.async.wait_group 0;" ::: "memory");
        __syncthreads();

        int sacc[8][4];
        #pragma unroll
        for (int nt = 0; nt < 8; ++nt)
            #pragma unroll
            for (int i = 0; i < 4; ++i) sacc[nt][i] = 0;

        #pragma unroll
        for (int kh = 0; kh < 3; ++kh) {
            #pragma unroll
            for (int kw = 0; kw < 3; ++kw) {
                const int tap = kh * 3 + kw;
                #pragma unroll
                for (int kc = 0; kc < 2; ++kc) {
                    u32 br[16];
                    const u32 bk = bbase_t + tap * BTAP + kc * 32;
                    ldm4(&br[0],  bk);
                    ldm4(&br[4],  bk + 16 * BPITCH);
                    ldm4(&br[8],  bk + 32 * BPITCH);
                    ldm4(&br[12], bk + 48 * BPITCH);
                    u32 a0[4];
                    const u32 ka = abase_t + (kh * 114 + kw) * APITCH + d * 64 + kc * 32;
                    ldm4(a0, ka);
                    #pragma unroll
                    for (int nt2 = 0; nt2 < 4; ++nt2) {
                        imma16832(sacc[2 * nt2],     a0, br[nt2 * 4],     br[nt2 * 4 + 2]);
                        imma16832(sacc[2 * nt2 + 1], a0, br[nt2 * 4 + 1], br[nt2 * 4 + 3]);
                    }
                }
            }
        }
        const float sc = (d == 0) ? 0.0625f
                       : (d == 1) ? 4.8828125e-4f : 3.814697265625e-6f;
        #pragma unroll
        for (int nt = 0; nt < 8; ++nt)
            #pragma unroll
            for (int i = 0; i < 4; ++i)
                facc[nt][i] = fmaf(sc, (float)sacc[nt][i], facc[nt][i]);
    }

    // ---- epilogue: facc -> smem [px][65], scale + LUT bucketize, store ----
    __syncthreads();
    float* sum = reinterpret_cast<float*>(smem);
    #pragma unroll
    for (int nt = 0; nt < 8; ++nt)
        #pragma unroll
        for (int i = 0; i < 4; ++i) {
            const int row = warp * 16 + (lane >> 2) + ((i >> 1) << 3);
            const int col = nt * 8 + ((lane & 3) << 1) + (i & 1);
            sum[row * 65 + col] = facc[nt][i];
        }
    __syncthreads();

    const int j = tid >> 1;              // pixel 0..255
    const int ch = (tid & 1) << 5;       // co half: 0 or 32
    const int s = s0 + j;
    const int rimg = s / 114 - 1;
    const int c = s - (rimg + 1) * 114;
    if (c < 112 && rimg < 112) {
        const int q = rimg * 112 + c;
        float* op = out + (size_t)n * 64 * 12544 + q + (size_t)ch * 12544;
        const float* sl = reinterpret_cast<const float*>(smem + LUT_OFF) + ch * 7;
        const float* ws = reinterpret_cast<const float*>(smem + WS_OFF) + ch;
        const float* sv = sum + j * 65 + ch;
        #pragma unroll 4
        for (int co = 0; co < 32; ++co) {
            const float v = sv[co] * ws[co];
            const float* tt = sl + co * 7;
            const float t0 = tt[0], t1 = tt[1], t2 = tt[2], t3 = tt[3],
                        t4 = tt[4], t5 = tt[5], t6 = tt[6];
            float r = v;
            if (v <= t0)            r = 0.f;
            if (v > t0 && v < t1)   r = 1.f;
            if (v >= t1 && v <= t2) r = 2.f;
            if (v > t2 && v < t3)   r = 3.f;
            if (v >= t3 && v <= t4) r = 4.f;
            if (v > t4 && v < t5)   r = 5.f;
            if (v >= t5 && v <= t6) r = 6.f;
            if (v > t6)             r = 7.f;
            op[(size_t)co * 12544] = r;
        }
    }
}

// ---------------------------------------------------------------------------
extern "C" void kernel_launch(void* const* d_in, const int* in_sizes, int n_in,
                              void* d_out, int out_size) {
    (void)in_sizes; (void)n_in; (void)out_size;
    const float* x   = (const float*)d_in[0];
    const float* w   = (const float*)d_in[1];
    const float* lut = (const float*)d_in[2];
    float* out = (float*)d_out;

    cudaFuncSetAttribute(conv_mma_kernel,
                         cudaFuncAttributeMaxDynamicSharedMemorySize, SMEM_TOTAL);

    binarize_kernel<<<64, 576>>>(w);
    pad_zero_kernel<<<33, 256>>>();
    convert_kernel<<<dim3(392, 32), 256>>>(x);
    conv_mma_kernel<<<dim3(50, 32), 512, SMEM_TOTAL>>>(lut, out);
}